// round 5
// baseline (speedup 1.0000x reference)
#include <cuda_runtime.h>
#include <math.h>

#define SEQ_LEN   65536
#define HIDDEN    1024
#define ROWS_PER_BLOCK 16
#define MV_BLOCKS (SEQ_LEN / ROWS_PER_BLOCK)   // 4096
#define EXP_BLOCKS 64                          // 64 x 256 thr x 4 elem = 65536

// Scratch (allocation-free requirement -> __device__ globals)
__device__ float g_pmax[MV_BLOCKS];
__device__ float g_psum[EXP_BLOCKS];

// ---------------------------------------------------------------------------
// Deterministic global max from the 4096 per-block partials (16 KB, L2-hot).
// Called identically from K2 and K3 -> bitwise-identical M everywhere.
// ---------------------------------------------------------------------------
__device__ __forceinline__ float block_global_max(
    const float* __restrict__ pmax, float* ws, int tid, int lane, int warp)
{
    float m = -INFINITY;
#pragma unroll
    for (int k = 0; k < 16; k++)
        m = fmaxf(m, pmax[tid + k * 256]);
#pragma unroll
    for (int o = 16; o > 0; o >>= 1)
        m = fmaxf(m, __shfl_xor_sync(0xffffffff, m, o));
    if (lane == 0) ws[warp] = m;
    __syncthreads();
    float M = fmaxf(fmaxf(fmaxf(ws[0], ws[1]), fmaxf(ws[2], ws[3])),
                    fmaxf(fmaxf(ws[4], ws[5]), fmaxf(ws[6], ws[7])));
    __syncthreads();   // ws reused by callers
    return M;
}

// ---------------------------------------------------------------------------
// K1: energies[r] = enc[r,:] . hidden ; per-block partial max
// 512 threads = 16 warps, 1 warp per row. 8x LDG.128 per lane (MLP=8).
// ---------------------------------------------------------------------------
__global__ __launch_bounds__(512) void matvec_kernel(
    const float* __restrict__ hidden,
    const float* __restrict__ enc,
    float* __restrict__ energies,
    float* __restrict__ pmax)
{
    __shared__ float sh[HIDDEN];
    __shared__ float wres[ROWS_PER_BLOCK];

    const int tid  = threadIdx.x;
    const int warp = tid >> 5;
    const int lane = tid & 31;

    if (tid < 256)
        reinterpret_cast<float4*>(sh)[tid] =
            reinterpret_cast<const float4*>(hidden)[tid];
    __syncthreads();

    const int row = blockIdx.x * ROWS_PER_BLOCK + warp;
    const float4* rp = reinterpret_cast<const float4*>(
        enc + (size_t)row * HIDDEN);
    const float4* hp = reinterpret_cast<const float4*>(sh);

    // Front-batch 8 global loads for MLP, then FMA against shared.
    float4 v[8];
#pragma unroll
    for (int k = 0; k < 8; k++)
        v[k] = rp[lane + k * 32];

    float acc = 0.0f;
#pragma unroll
    for (int k = 0; k < 8; k++) {
        float4 h = hp[lane + k * 32];
        acc = fmaf(v[k].x, h.x, acc);
        acc = fmaf(v[k].y, h.y, acc);
        acc = fmaf(v[k].z, h.z, acc);
        acc = fmaf(v[k].w, h.w, acc);
    }

#pragma unroll
    for (int o = 16; o > 0; o >>= 1)
        acc += __shfl_xor_sync(0xffffffff, acc, o);

    if (lane == 0) {
        energies[row] = acc;
        wres[warp] = acc;
    }
    __syncthreads();

    if (warp == 0) {
        float m = (lane < ROWS_PER_BLOCK) ? wres[lane] : -INFINITY;
#pragma unroll
        for (int o = 8; o > 0; o >>= 1)
            m = fmaxf(m, __shfl_xor_sync(0xffffffff, m, o));
        if (lane == 0) pmax[blockIdx.x] = m;
    }
}

// ---------------------------------------------------------------------------
// K2: global max (deterministic, per-block) + per-block sum of exp.
// Reads energies (read-only); writes only psum[block].
// ---------------------------------------------------------------------------
__global__ __launch_bounds__(256) void sumexp_kernel(
    const float* __restrict__ e,
    const float* __restrict__ pmax,
    float* __restrict__ psum)
{
    __shared__ float ws[8];
    const int tid  = threadIdx.x;
    const int lane = tid & 31;
    const int warp = tid >> 5;

    const float M = block_global_max(pmax, ws, tid, lane, warp);

    const int i = blockIdx.x * 256 + tid;
    float4 v = reinterpret_cast<const float4*>(e)[i];
    float s = (expf(v.x - M) + expf(v.y - M))
            + (expf(v.z - M) + expf(v.w - M));

#pragma unroll
    for (int o = 16; o > 0; o >>= 1)
        s += __shfl_xor_sync(0xffffffff, s, o);
    if (lane == 0) ws[warp] = s;
    __syncthreads();
    if (warp == 0) {
        float t = (lane < 8) ? ws[lane] : 0.0f;
#pragma unroll
        for (int o = 4; o > 0; o >>= 1)
            t += __shfl_xor_sync(0xffffffff, t, o);
        if (lane == 0) psum[blockIdx.x] = t;
    }
}

// ---------------------------------------------------------------------------
// K3: recompute identical M, reduce the 64 partial sums (deterministic),
// write out[i] = exp(e[i]-M) * inv  in one pass.
// ---------------------------------------------------------------------------
__global__ __launch_bounds__(256) void scale_kernel(
    float* __restrict__ e,
    const float* __restrict__ pmax,
    const float* __restrict__ psum)
{
    __shared__ float ws[8];
    const int tid  = threadIdx.x;
    const int lane = tid & 31;
    const int warp = tid >> 5;

    const float M = block_global_max(pmax, ws, tid, lane, warp);

    // Deterministic sum of 64 partials: warp 0 reduces, broadcasts via shared.
    if (warp == 0) {
        float s = psum[lane] + psum[lane + 32];
#pragma unroll
        for (int o = 16; o > 0; o >>= 1)
            s += __shfl_xor_sync(0xffffffff, s, o);
        if (lane == 0) ws[0] = s;
    }
    __syncthreads();
    const float inv = 1.0f / ws[0];

    const int i = blockIdx.x * 256 + tid;
    float4 v = reinterpret_cast<float4*>(e)[i];
    v.x = expf(v.x - M) * inv;
    v.y = expf(v.y - M) * inv;
    v.z = expf(v.z - M) * inv;
    v.w = expf(v.w - M) * inv;
    reinterpret_cast<float4*>(e)[i] = v;
}

// ---------------------------------------------------------------------------
extern "C" void kernel_launch(void* const* d_in, const int* in_sizes, int n_in,
                              void* d_out, int out_size)
{
    // Autodetect input order by element count (hidden = 1024, enc = 64M).
    const float* hidden;
    const float* enc;
    if (in_sizes[0] == HIDDEN) {
        hidden = (const float*)d_in[0];
        enc    = (const float*)d_in[1];
    } else {
        enc    = (const float*)d_in[0];
        hidden = (const float*)d_in[1];
    }
    float* out = (float*)d_out;                           // [65536] == [1,1,S]

    float* pmax;  cudaGetSymbolAddress((void**)&pmax,  g_pmax);
    float* psum;  cudaGetSymbolAddress((void**)&psum,  g_psum);

    matvec_kernel<<<MV_BLOCKS, 512>>>(hidden, enc, out, pmax);
    sumexp_kernel<<<EXP_BLOCKS, 256>>>(out, pmax, psum);
    scale_kernel<<<EXP_BLOCKS, 256>>>(out, pmax, psum);
}